// round 2
// baseline (speedup 1.0000x reference)
#include <cuda_runtime.h>

// Problem constants (fixed for this dataset)
#define NN 50000
#define EE 800000
#define ET (EE + NN)      // 850000 edges incl. self loops
#define H1 4
#define C1 64
#define D1 256            // H1*C1
#define C2 64
#define IN1 128
#define NEG_SLOPE 0.2f

// ---------------- scratch (device globals, no runtime alloc) ----------------
__device__ float    g_h1 [(size_t)NN * D1];   // x @ W1
__device__ float    g_acc1[(size_t)NN * D1];  // layer1 aggregation / relu output
__device__ float    g_as1[NN * H1];
__device__ float    g_ad1[NN * H1];
__device__ unsigned g_m1 [NN * H1];           // ordered-float encoded max
__device__ float    g_s1 [NN * H1];
__device__ float    g_ex1[(size_t)ET * H1];
__device__ float    g_h2 [(size_t)NN * C2];
__device__ float    g_as2[NN];
__device__ float    g_ad2[NN];
__device__ unsigned g_m2 [NN];
__device__ float    g_s2 [NN];
__device__ float    g_ex2[ET];

// ---------------- helpers ----------------
__device__ __forceinline__ unsigned enc_f(float f) {
    unsigned u = __float_as_uint(f);
    return (u & 0x80000000u) ? ~u : (u | 0x80000000u);
}
__device__ __forceinline__ float dec_f(unsigned u) {
    return (u & 0x80000000u) ? __uint_as_float(u & 0x7FFFFFFFu)
                             : __uint_as_float(~u);
}

// ---------------- zero-init all scratch + output ----------------
// total floats to zero: acc1 (NN*D1) + m1/s1 (2*NN*H1) + m2/s2 (2*NN) + out (NN*C2)
__global__ void zero_kernel(float* __restrict__ out) {
    const int n_acc1 = NN * D1;           // 12.8M
    const int n_mh   = NN * H1;           // 200k
    const int n_out  = NN * C2;           // 3.2M
    int stride = gridDim.x * blockDim.x;
    for (int i = blockIdx.x * blockDim.x + threadIdx.x; i < n_acc1; i += stride)
        g_acc1[i] = 0.f;
    for (int i = blockIdx.x * blockDim.x + threadIdx.x; i < n_mh; i += stride) {
        g_m1[i] = 0u; g_s1[i] = 0.f;
    }
    for (int i = blockIdx.x * blockDim.x + threadIdx.x; i < NN; i += stride) {
        g_m2[i] = 0u; g_s2[i] = 0.f;
    }
    for (int i = blockIdx.x * blockDim.x + threadIdx.x; i < n_out; i += stride)
        out[i] = 0.f;
}

// ---------------- tiled SGEMM: C[M,N] = A[M,K] @ B[K,N] ----------------
// 64x64 tile, BK=16, 256 threads, 4x4 micro-tile. N, K multiples of 64/16.
__global__ void sgemm_kernel(const float* __restrict__ A,
                             const float* __restrict__ B,
                             float* __restrict__ C, int M, int N, int K) {
    __shared__ float As[16][64];
    __shared__ float Bs[16][64];
    int tid = threadIdx.x;
    int tx = tid & 15, ty = tid >> 4;
    int row0 = blockIdx.y * 64, col0 = blockIdx.x * 64;
    float acc[4][4] = {};
    for (int k0 = 0; k0 < K; k0 += 16) {
        #pragma unroll
        for (int i = 0; i < 4; i++) {
            int idx = tid + i * 256;
            int r = idx >> 4, c = idx & 15;      // A tile: 64 rows x 16 k
            int gr = row0 + r;
            As[c][r] = (gr < M) ? A[(size_t)gr * K + k0 + c] : 0.f;
            int br = idx >> 6, bc = idx & 63;    // B tile: 16 k x 64 cols
            Bs[br][bc] = B[(size_t)(k0 + br) * N + col0 + bc];
        }
        __syncthreads();
        #pragma unroll
        for (int k = 0; k < 16; k++) {
            float ra[4], rb[4];
            #pragma unroll
            for (int a = 0; a < 4; a++) ra[a] = As[k][ty * 4 + a];
            #pragma unroll
            for (int b = 0; b < 4; b++) rb[b] = Bs[k][tx * 4 + b];
            #pragma unroll
            for (int a = 0; a < 4; a++)
                #pragma unroll
                for (int b = 0; b < 4; b++) acc[a][b] += ra[a] * rb[b];
        }
        __syncthreads();
    }
    #pragma unroll
    for (int a = 0; a < 4; a++) {
        int gr = row0 + ty * 4 + a;
        if (gr < M) {
            #pragma unroll
            for (int b = 0; b < 4; b++)
                C[(size_t)gr * N + col0 + tx * 4 + b] = acc[a][b];
        }
    }
}

// ---------------- per-node attention coefficients, layer 1 ----------------
// one warp per node; lane covers 8 contiguous cols (all within one head)
__global__ void alpha1_kernel(const float* __restrict__ a_src,
                              const float* __restrict__ a_dst) {
    int w = (blockIdx.x * blockDim.x + threadIdx.x) >> 5;
    int lane = threadIdx.x & 31;
    if (w >= NN) return;
    const float4* hp = reinterpret_cast<const float4*>(g_h1 + (size_t)w * D1);
    float4 v0 = hp[2 * lane];
    float4 v1 = hp[2 * lane + 1];
    int head = lane >> 3;
    int cb = (lane & 7) * 8;
    const float* sa = a_src + head * C1 + cb;
    const float* da = a_dst + head * C1 + cb;
    float ps = v0.x * sa[0] + v0.y * sa[1] + v0.z * sa[2] + v0.w * sa[3]
             + v1.x * sa[4] + v1.y * sa[5] + v1.z * sa[6] + v1.w * sa[7];
    float pd = v0.x * da[0] + v0.y * da[1] + v0.z * da[2] + v0.w * da[3]
             + v1.x * da[4] + v1.y * da[5] + v1.z * da[6] + v1.w * da[7];
    #pragma unroll
    for (int o = 1; o < 8; o <<= 1) {
        ps += __shfl_xor_sync(0xFFFFFFFFu, ps, o);
        pd += __shfl_xor_sync(0xFFFFFFFFu, pd, o);
    }
    if ((lane & 7) == 0) {
        g_as1[w * H1 + head] = ps;
        g_ad1[w * H1 + head] = pd;
    }
}

// ---------------- per-node attention coefficients, layer 2 (H=1) ----------
__global__ void alpha2_kernel(const float* __restrict__ a_src,
                              const float* __restrict__ a_dst) {
    int w = (blockIdx.x * blockDim.x + threadIdx.x) >> 5;
    int lane = threadIdx.x & 31;
    if (w >= NN) return;
    float2 v = reinterpret_cast<const float2*>(g_h2 + (size_t)w * C2)[lane];
    float ps = v.x * a_src[2 * lane] + v.y * a_src[2 * lane + 1];
    float pd = v.x * a_dst[2 * lane] + v.y * a_dst[2 * lane + 1];
    #pragma unroll
    for (int o = 1; o < 32; o <<= 1) {
        ps += __shfl_xor_sync(0xFFFFFFFFu, ps, o);
        pd += __shfl_xor_sync(0xFFFFFFFFu, pd, o);
    }
    if (lane == 0) { g_as2[w] = ps; g_ad2[w] = pd; }
}

// ---------------- edge logit max pass, layer1 (H1 heads per thread grp) ----
__global__ void edge_max1_kernel(const int* __restrict__ ei) {
    int idx = blockIdx.x * blockDim.x + threadIdx.x;
    if (idx >= ET * H1) return;
    int e = idx >> 2, h = idx & 3;
    int s, d;
    if (e < EE) { s = ei[e]; d = ei[EE + e]; } else { s = d = e - EE; }
    float v = g_as1[s * H1 + h] + g_ad1[d * H1 + h];
    v = (v > 0.f) ? v : NEG_SLOPE * v;
    atomicMax(&g_m1[d * H1 + h], enc_f(v));
}

__global__ void edge_exp1_kernel(const int* __restrict__ ei) {
    int idx = blockIdx.x * blockDim.x + threadIdx.x;
    if (idx >= ET * H1) return;
    int e = idx >> 2, h = idx & 3;
    int s, d;
    if (e < EE) { s = ei[e]; d = ei[EE + e]; } else { s = d = e - EE; }
    float v = g_as1[s * H1 + h] + g_ad1[d * H1 + h];
    v = (v > 0.f) ? v : NEG_SLOPE * v;
    float exv = __expf(v - dec_f(g_m1[d * H1 + h]));
    g_ex1[idx] = exv;
    atomicAdd(&g_s1[d * H1 + h], exv);
}

// ---------------- edge logit passes, layer2 (H=1) ----------------
__global__ void edge_max2_kernel(const int* __restrict__ ei) {
    int e = blockIdx.x * blockDim.x + threadIdx.x;
    if (e >= ET) return;
    int s, d;
    if (e < EE) { s = ei[e]; d = ei[EE + e]; } else { s = d = e - EE; }
    float v = g_as2[s] + g_ad2[d];
    v = (v > 0.f) ? v : NEG_SLOPE * v;
    atomicMax(&g_m2[d], enc_f(v));
}

__global__ void edge_exp2_kernel(const int* __restrict__ ei) {
    int e = blockIdx.x * blockDim.x + threadIdx.x;
    if (e >= ET) return;
    int s, d;
    if (e < EE) { s = ei[e]; d = ei[EE + e]; } else { s = d = e - EE; }
    float v = g_as2[s] + g_ad2[d];
    v = (v > 0.f) ? v : NEG_SLOPE * v;
    float exv = __expf(v - dec_f(g_m2[d]));
    g_ex2[e] = exv;
    atomicAdd(&g_s2[d], exv);
}

// ---------------- layer1 aggregation: warp per edge, 256 cols --------------
__global__ void aggr1_kernel(const int* __restrict__ ei) {
    int w = (blockIdx.x * blockDim.x + threadIdx.x) >> 5;
    int lane = threadIdx.x & 31;
    if (w >= ET) return;
    int s, d;
    if (w < EE) { s = ei[w]; d = ei[EE + w]; } else { s = d = w - EE; }
    int head = lane >> 3;
    float alpha = g_ex1[(size_t)w * H1 + head] / (g_s1[d * H1 + head] + 1e-16f);
    const float4* hp = reinterpret_cast<const float4*>(g_h1 + (size_t)s * D1);
    float4 v0 = hp[2 * lane];
    float4 v1 = hp[2 * lane + 1];
    float* ap = g_acc1 + (size_t)d * D1 + lane * 8;
    atomicAdd(ap + 0, v0.x * alpha);
    atomicAdd(ap + 1, v0.y * alpha);
    atomicAdd(ap + 2, v0.z * alpha);
    atomicAdd(ap + 3, v0.w * alpha);
    atomicAdd(ap + 4, v1.x * alpha);
    atomicAdd(ap + 5, v1.y * alpha);
    atomicAdd(ap + 6, v1.z * alpha);
    atomicAdd(ap + 7, v1.w * alpha);
}

// ---------------- layer2 aggregation: warp per edge, 64 cols ---------------
__global__ void aggr2_kernel(const int* __restrict__ ei,
                             float* __restrict__ out) {
    int w = (blockIdx.x * blockDim.x + threadIdx.x) >> 5;
    int lane = threadIdx.x & 31;
    if (w >= ET) return;
    int s, d;
    if (w < EE) { s = ei[w]; d = ei[EE + w]; } else { s = d = w - EE; }
    float alpha = g_ex2[w] / (g_s2[d] + 1e-16f);
    float2 v = reinterpret_cast<const float2*>(g_h2 + (size_t)s * C2)[lane];
    float* op = out + (size_t)d * C2 + 2 * lane;
    atomicAdd(op + 0, v.x * alpha);
    atomicAdd(op + 1, v.y * alpha);
}

// ---------------- bias + relu (layer1, in place) ----------------
__global__ void bias_relu_kernel(const float* __restrict__ b) {
    int idx = blockIdx.x * blockDim.x + threadIdx.x;
    if (idx >= NN * D1) return;
    float v = g_acc1[idx] + b[idx & (D1 - 1)];
    g_acc1[idx] = v > 0.f ? v : 0.f;
}

// ---------------- bias (layer2 output) ----------------
__global__ void bias2_kernel(float* __restrict__ out,
                             const float* __restrict__ b) {
    int idx = blockIdx.x * blockDim.x + threadIdx.x;
    if (idx >= NN * C2) return;
    out[idx] += b[idx & (C2 - 1)];
}

// device-global address helpers (compiled device code may use symbols
// directly; for sgemm we need raw pointers, so use small wrapper kernels
// that write into the globals directly)
__global__ void copy_ptr_noop() {}

extern "C" void kernel_launch(void* const* d_in, const int* in_sizes, int n_in,
                              void* d_out, int out_size) {
    const float* x     = (const float*)d_in[0];
    const int*   ei    = (const int*)d_in[1];     // int32 (jax x64 disabled)
    const float* W1    = (const float*)d_in[2];
    const float* at_s1 = (const float*)d_in[3];
    const float* at_d1 = (const float*)d_in[4];
    const float* b1    = (const float*)d_in[5];
    const float* W2    = (const float*)d_in[6];
    const float* at_s2 = (const float*)d_in[7];
    const float* at_d2 = (const float*)d_in[8];
    const float* b2    = (const float*)d_in[9];
    float* out = (float*)d_out;

    // scratch pointers for sgemm (host needs raw addresses)
    static float* p_h1   = nullptr;
    static float* p_acc1 = nullptr;
    static float* p_h2   = nullptr;
    if (!p_h1) {   // address lookup only (no allocation); deterministic
        cudaGetSymbolAddress((void**)&p_h1, g_h1);
        cudaGetSymbolAddress((void**)&p_acc1, g_acc1);
        cudaGetSymbolAddress((void**)&p_h2, g_h2);
    }

    // zero scratch + output
    zero_kernel<<<512, 256>>>(out);

    // ---- layer 1 ----
    sgemm_kernel<<<dim3(D1 / 64, (NN + 63) / 64), 256>>>(x, W1, p_h1, NN, D1, IN1);
    alpha1_kernel<<<(NN + 7) / 8, 256>>>(at_s1, at_d1);
    edge_max1_kernel<<<(ET * H1 + 255) / 256, 256>>>(ei);
    edge_exp1_kernel<<<(ET * H1 + 255) / 256, 256>>>(ei);
    aggr1_kernel<<<(ET + 7) / 8, 256>>>(ei);
    bias_relu_kernel<<<(NN * D1 + 255) / 256, 256>>>(b1);

    // ---- layer 2 ----
    sgemm_kernel<<<dim3(C2 / 64, (NN + 63) / 64), 256>>>(p_acc1, W2, p_h2, NN, C2, D1);
    alpha2_kernel<<<(NN + 7) / 8, 256>>>(at_s2, at_d2);
    edge_max2_kernel<<<(ET + 255) / 256, 256>>>(ei);
    edge_exp2_kernel<<<(ET + 255) / 256, 256>>>(ei);
    aggr2_kernel<<<(ET + 7) / 8, 256>>>(ei, out);
    bias2_kernel<<<(NN * C2 + 255) / 256, 256>>>(out, b2);
}

// round 3
// speedup vs baseline: 3.2685x; 3.2685x over previous
#include <cuda_runtime.h>
#include <math.h>

// Problem constants (fixed for this dataset)
#define NN 50000
#define EE 800000
#define ET (EE + NN)      // 850000 edges incl. self loops
#define H1 4
#define C1 64
#define D1 256            // H1*C1
#define C2 64
#define IN1 128
#define NEG_SLOPE 0.2f

// ---------------- scratch (device globals, no runtime alloc) ----------------
__device__ float g_h1 [(size_t)NN * D1];   // x @ W1
__device__ float g_acc1[(size_t)NN * D1];  // layer1 output (post bias+relu)
__device__ float g_as1[NN * H1];
__device__ float g_ad1[NN * H1];
__device__ float g_h2 [(size_t)NN * C2];
__device__ float g_as2[NN];
__device__ float g_ad2[NN];
// CSR by dst
__device__ int g_deg[NN];
__device__ int g_cur[NN];
__device__ int g_row[NN + 1];
__device__ int g_srcs[ET];

__device__ __forceinline__ float lrelu(float v) {
    return v > 0.f ? v : NEG_SLOPE * v;
}

// ---------------- CSR build ----------------
__global__ void zero_counts_kernel() {
    int i = blockIdx.x * blockDim.x + threadIdx.x;
    if (i < NN) { g_deg[i] = 0; g_cur[i] = 0; }
}

__global__ void hist_kernel(const int* __restrict__ ei) {
    int e = blockIdx.x * blockDim.x + threadIdx.x;
    if (e >= ET) return;
    int d = (e < EE) ? ei[EE + e] : (e - EE);
    atomicAdd(&g_deg[d], 1);
}

// single-block exclusive scan of g_deg -> g_row  (1024 threads)
__global__ void scan_kernel() {
    __shared__ int warp_sums[32];
    const int CHUNK = (NN + 1023) / 1024;   // 49
    int t = threadIdx.x;
    int lane = t & 31, wid = t >> 5;
    int start = t * CHUNK;
    int local = 0;
    for (int i = 0; i < CHUNK; i++) {
        int idx = start + i;
        if (idx < NN) local += g_deg[idx];
    }
    int v = local;
    #pragma unroll
    for (int o = 1; o < 32; o <<= 1) {
        int n = __shfl_up_sync(0xFFFFFFFFu, v, o);
        if (lane >= o) v += n;
    }
    if (lane == 31) warp_sums[wid] = v;
    __syncthreads();
    if (wid == 0) {
        int w = warp_sums[lane];
        #pragma unroll
        for (int o = 1; o < 32; o <<= 1) {
            int n = __shfl_up_sync(0xFFFFFFFFu, w, o);
            if (lane >= o) w += n;
        }
        warp_sums[lane] = w;
    }
    __syncthreads();
    int excl = v - local + (wid > 0 ? warp_sums[wid - 1] : 0);
    int run = excl;
    for (int i = 0; i < CHUNK; i++) {
        int idx = start + i;
        if (idx < NN) {
            int dg = g_deg[idx];
            g_row[idx] = run;
            run += dg;
        }
    }
    if (t == 1023) g_row[NN] = run;   // == ET
}

__global__ void scatter_kernel(const int* __restrict__ ei) {
    int e = blockIdx.x * blockDim.x + threadIdx.x;
    if (e >= ET) return;
    int s, d;
    if (e < EE) { s = ei[e]; d = ei[EE + e]; } else { s = d = e - EE; }
    int pos = atomicAdd(&g_cur[d], 1);
    g_srcs[g_row[d] + pos] = s;
}

// ---------------- tiled SGEMM: C[M,N] = A[M,K] @ B[K,N] ----------------
__global__ void sgemm_kernel(const float* __restrict__ A,
                             const float* __restrict__ B,
                             float* __restrict__ C, int M, int N, int K) {
    __shared__ float As[16][64];
    __shared__ float Bs[16][64];
    int tid = threadIdx.x;
    int tx = tid & 15, ty = tid >> 4;
    int row0 = blockIdx.y * 64, col0 = blockIdx.x * 64;
    float acc[4][4] = {};
    for (int k0 = 0; k0 < K; k0 += 16) {
        #pragma unroll
        for (int i = 0; i < 4; i++) {
            int idx = tid + i * 256;
            int r = idx >> 4, c = idx & 15;
            int gr = row0 + r;
            As[c][r] = (gr < M) ? A[(size_t)gr * K + k0 + c] : 0.f;
            int br = idx >> 6, bc = idx & 63;
            Bs[br][bc] = B[(size_t)(k0 + br) * N + col0 + bc];
        }
        __syncthreads();
        #pragma unroll
        for (int k = 0; k < 16; k++) {
            float ra[4], rb[4];
            #pragma unroll
            for (int a = 0; a < 4; a++) ra[a] = As[k][ty * 4 + a];
            #pragma unroll
            for (int b = 0; b < 4; b++) rb[b] = Bs[k][tx * 4 + b];
            #pragma unroll
            for (int a = 0; a < 4; a++)
                #pragma unroll
                for (int b = 0; b < 4; b++) acc[a][b] += ra[a] * rb[b];
        }
        __syncthreads();
    }
    #pragma unroll
    for (int a = 0; a < 4; a++) {
        int gr = row0 + ty * 4 + a;
        if (gr < M) {
            #pragma unroll
            for (int b = 0; b < 4; b++)
                C[(size_t)gr * N + col0 + tx * 4 + b] = acc[a][b];
        }
    }
}

// ---------------- per-node attention coefficients, layer 1 ----------------
__global__ void alpha1_kernel(const float* __restrict__ a_src,
                              const float* __restrict__ a_dst) {
    int w = (blockIdx.x * blockDim.x + threadIdx.x) >> 5;
    int lane = threadIdx.x & 31;
    if (w >= NN) return;
    const float4* hp = reinterpret_cast<const float4*>(g_h1 + (size_t)w * D1);
    float4 v0 = hp[2 * lane];
    float4 v1 = hp[2 * lane + 1];
    int head = lane >> 3;
    int cb = (lane & 7) * 8;
    const float* sa = a_src + head * C1 + cb;
    const float* da = a_dst + head * C1 + cb;
    float ps = v0.x * sa[0] + v0.y * sa[1] + v0.z * sa[2] + v0.w * sa[3]
             + v1.x * sa[4] + v1.y * sa[5] + v1.z * sa[6] + v1.w * sa[7];
    float pd = v0.x * da[0] + v0.y * da[1] + v0.z * da[2] + v0.w * da[3]
             + v1.x * da[4] + v1.y * da[5] + v1.z * da[6] + v1.w * da[7];
    #pragma unroll
    for (int o = 1; o < 8; o <<= 1) {
        ps += __shfl_xor_sync(0xFFFFFFFFu, ps, o);
        pd += __shfl_xor_sync(0xFFFFFFFFu, pd, o);
    }
    if ((lane & 7) == 0) {
        g_as1[w * H1 + head] = ps;
        g_ad1[w * H1 + head] = pd;
    }
}

// ---------------- per-node attention coefficients, layer 2 (H=1) ----------
__global__ void alpha2_kernel(const float* __restrict__ a_src,
                              const float* __restrict__ a_dst) {
    int w = (blockIdx.x * blockDim.x + threadIdx.x) >> 5;
    int lane = threadIdx.x & 31;
    if (w >= NN) return;
    float2 v = reinterpret_cast<const float2*>(g_h2 + (size_t)w * C2)[lane];
    float ps = v.x * a_src[2 * lane] + v.y * a_src[2 * lane + 1];
    float pd = v.x * a_dst[2 * lane] + v.y * a_dst[2 * lane + 1];
    #pragma unroll
    for (int o = 1; o < 32; o <<= 1) {
        ps += __shfl_xor_sync(0xFFFFFFFFu, ps, o);
        pd += __shfl_xor_sync(0xFFFFFFFFu, pd, o);
    }
    if (lane == 0) { g_as2[w] = ps; g_ad2[w] = pd; }
}

// ---------------- fused layer1: softmax + gather-aggregate + bias + relu ---
// one warp per dst node; lane covers 8 cols (head = lane>>3)
__global__ void gat1_fused_kernel(const float* __restrict__ b1) {
    int w = (blockIdx.x * blockDim.x + threadIdx.x) >> 5;
    int lane = threadIdx.x & 31;
    if (w >= NN) return;
    int beg = g_row[w], end = g_row[w + 1];

    float4 adv = *reinterpret_cast<const float4*>(g_ad1 + w * H1);

    // pass A: per-head max over incoming edges
    float4 mx = make_float4(-INFINITY, -INFINITY, -INFINITY, -INFINITY);
    for (int i = beg + lane; i < end; i += 32) {
        int s = g_srcs[i];
        float4 a = *reinterpret_cast<const float4*>(g_as1 + s * H1);
        mx.x = fmaxf(mx.x, lrelu(a.x + adv.x));
        mx.y = fmaxf(mx.y, lrelu(a.y + adv.y));
        mx.z = fmaxf(mx.z, lrelu(a.z + adv.z));
        mx.w = fmaxf(mx.w, lrelu(a.w + adv.w));
    }
    #pragma unroll
    for (int o = 1; o < 32; o <<= 1) {
        mx.x = fmaxf(mx.x, __shfl_xor_sync(0xFFFFFFFFu, mx.x, o));
        mx.y = fmaxf(mx.y, __shfl_xor_sync(0xFFFFFFFFu, mx.y, o));
        mx.z = fmaxf(mx.z, __shfl_xor_sync(0xFFFFFFFFu, mx.z, o));
        mx.w = fmaxf(mx.w, __shfl_xor_sync(0xFFFFFFFFu, mx.w, o));
    }

    // pass B: per-head exp-sum
    float4 sm = make_float4(0.f, 0.f, 0.f, 0.f);
    for (int i = beg + lane; i < end; i += 32) {
        int s = g_srcs[i];
        float4 a = *reinterpret_cast<const float4*>(g_as1 + s * H1);
        sm.x += __expf(lrelu(a.x + adv.x) - mx.x);
        sm.y += __expf(lrelu(a.y + adv.y) - mx.y);
        sm.z += __expf(lrelu(a.z + adv.z) - mx.z);
        sm.w += __expf(lrelu(a.w + adv.w) - mx.w);
    }
    #pragma unroll
    for (int o = 1; o < 32; o <<= 1) {
        sm.x += __shfl_xor_sync(0xFFFFFFFFu, sm.x, o);
        sm.y += __shfl_xor_sync(0xFFFFFFFFu, sm.y, o);
        sm.z += __shfl_xor_sync(0xFFFFFFFFu, sm.z, o);
        sm.w += __shfl_xor_sync(0xFFFFFFFFu, sm.w, o);
    }

    // lane-specific head constants
    int head = lane >> 3;
    float mh  = (head == 0) ? mx.x : (head == 1) ? mx.y : (head == 2) ? mx.z : mx.w;
    float shv = (head == 0) ? sm.x : (head == 1) ? sm.y : (head == 2) ? sm.z : sm.w;
    float adh = (head == 0) ? adv.x : (head == 1) ? adv.y : (head == 2) ? adv.z : adv.w;
    float inv = 1.f / (shv + 1e-16f);

    // pass C: gather + accumulate (all lanes walk all edges together)
    float acc[8] = {};
    for (int i = beg; i < end; i++) {
        int s = g_srcs[i];                               // broadcast load
        float ash = g_as1[s * H1 + head];
        float alpha = __expf(lrelu(ash + adh) - mh) * inv;
        const float4* hp = reinterpret_cast<const float4*>(g_h1 + (size_t)s * D1);
        float4 v0 = hp[2 * lane];
        float4 v1 = hp[2 * lane + 1];
        acc[0] += v0.x * alpha; acc[1] += v0.y * alpha;
        acc[2] += v0.z * alpha; acc[3] += v0.w * alpha;
        acc[4] += v1.x * alpha; acc[5] += v1.y * alpha;
        acc[6] += v1.z * alpha; acc[7] += v1.w * alpha;
    }

    // write with bias + relu
    int cb = lane * 8;
    float* op = g_acc1 + (size_t)w * D1 + cb;
    #pragma unroll
    for (int j = 0; j < 8; j++) {
        float v = acc[j] + b1[cb + j];
        op[j] = v > 0.f ? v : 0.f;
    }
}

// ---------------- fused layer2: softmax + gather-aggregate + bias ----------
// one warp per dst node; lane covers 2 cols
__global__ void gat2_fused_kernel(const float* __restrict__ b2,
                                  float* __restrict__ out) {
    int w = (blockIdx.x * blockDim.x + threadIdx.x) >> 5;
    int lane = threadIdx.x & 31;
    if (w >= NN) return;
    int beg = g_row[w], end = g_row[w + 1];

    float ad = g_ad2[w];

    float mxv = -INFINITY;
    for (int i = beg + lane; i < end; i += 32) {
        int s = g_srcs[i];
        mxv = fmaxf(mxv, lrelu(g_as2[s] + ad));
    }
    #pragma unroll
    for (int o = 1; o < 32; o <<= 1)
        mxv = fmaxf(mxv, __shfl_xor_sync(0xFFFFFFFFu, mxv, o));

    float smv = 0.f;
    for (int i = beg + lane; i < end; i += 32) {
        int s = g_srcs[i];
        smv += __expf(lrelu(g_as2[s] + ad) - mxv);
    }
    #pragma unroll
    for (int o = 1; o < 32; o <<= 1)
        smv += __shfl_xor_sync(0xFFFFFFFFu, smv, o);
    float inv = 1.f / (smv + 1e-16f);

    float a0 = 0.f, a1 = 0.f;
    for (int i = beg; i < end; i++) {
        int s = g_srcs[i];
        float alpha = __expf(lrelu(g_as2[s] + ad) - mxv) * inv;
        float2 v = reinterpret_cast<const float2*>(g_h2 + (size_t)s * C2)[lane];
        a0 += v.x * alpha;
        a1 += v.y * alpha;
    }
    float* op = out + (size_t)w * C2 + 2 * lane;
    op[0] = a0 + b2[2 * lane];
    op[1] = a1 + b2[2 * lane + 1];
}

extern "C" void kernel_launch(void* const* d_in, const int* in_sizes, int n_in,
                              void* d_out, int out_size) {
    const float* x     = (const float*)d_in[0];
    const int*   ei    = (const int*)d_in[1];     // int32
    const float* W1    = (const float*)d_in[2];
    const float* at_s1 = (const float*)d_in[3];
    const float* at_d1 = (const float*)d_in[4];
    const float* b1    = (const float*)d_in[5];
    const float* W2    = (const float*)d_in[6];
    const float* at_s2 = (const float*)d_in[7];
    const float* at_d2 = (const float*)d_in[8];
    const float* b2    = (const float*)d_in[9];
    float* out = (float*)d_out;

    static float* p_h1   = nullptr;
    static float* p_acc1 = nullptr;
    static float* p_h2   = nullptr;
    if (!p_h1) {   // address lookup only (no allocation)
        cudaGetSymbolAddress((void**)&p_h1, g_h1);
        cudaGetSymbolAddress((void**)&p_acc1, g_acc1);
        cudaGetSymbolAddress((void**)&p_h2, g_h2);
    }

    // ---- CSR build (shared by both layers) ----
    zero_counts_kernel<<<(NN + 255) / 256, 256>>>();
    hist_kernel<<<(ET + 255) / 256, 256>>>(ei);
    scan_kernel<<<1, 1024>>>();
    scatter_kernel<<<(ET + 255) / 256, 256>>>(ei);

    // ---- layer 1 ----
    sgemm_kernel<<<dim3(D1 / 64, (NN + 63) / 64), 256>>>(x, W1, p_h1, NN, D1, IN1);
    alpha1_kernel<<<(NN + 7) / 8, 256>>>(at_s1, at_d1);
    gat1_fused_kernel<<<(NN + 7) / 8, 256>>>(b1);

    // ---- layer 2 ----
    sgemm_kernel<<<dim3(C2 / 64, (NN + 63) / 64), 256>>>(p_acc1, W2, p_h2, NN, C2, D1);
    alpha2_kernel<<<(NN + 7) / 8, 256>>>(at_s2, at_d2);
    gat2_fused_kernel<<<(NN + 7) / 8, 256>>>(b2, out);
}

// round 4
// speedup vs baseline: 3.7197x; 1.1380x over previous
#include <cuda_runtime.h>
#include <math.h>

// Problem constants (fixed for this dataset)
#define NN 50000
#define EE 800000
#define ET (EE + NN)      // 850000 edges incl. self loops
#define H1 4
#define C1 64
#define D1 256            // H1*C1
#define C2 64
#define IN1 128
#define NEG_SLOPE 0.2f

// ---------------- scratch (device globals, no runtime alloc) ----------------
__device__ float g_h1 [(size_t)NN * D1];   // x @ W1
__device__ float g_acc1[(size_t)NN * D1];  // layer1 output (post bias+relu)
__device__ float g_as1[NN * H1];
__device__ float g_ad1[NN * H1];
__device__ float g_h2 [(size_t)NN * C2];
__device__ float g_as2[NN];
__device__ float g_ad2[NN];
// CSR by dst
__device__ int g_deg[NN];
__device__ int g_cur[NN];
__device__ int g_row[NN + 1];
__device__ int g_srcs[ET];

__device__ __forceinline__ float lrelu(float v) {
    return v > 0.f ? v : NEG_SLOPE * v;
}

// ---------------- CSR build ----------------
__global__ void zero_counts_kernel() {
    int i = blockIdx.x * blockDim.x + threadIdx.x;
    if (i < NN) { g_deg[i] = 0; g_cur[i] = 0; }
}

__global__ void hist_kernel(const int* __restrict__ ei) {
    int e = blockIdx.x * blockDim.x + threadIdx.x;
    if (e >= ET) return;
    int d = (e < EE) ? ei[EE + e] : (e - EE);
    atomicAdd(&g_deg[d], 1);
}

// single-block exclusive scan of g_deg -> g_row  (1024 threads)
__global__ void scan_kernel() {
    __shared__ int warp_sums[32];
    const int CHUNK = (NN + 1023) / 1024;   // 49
    int t = threadIdx.x;
    int lane = t & 31, wid = t >> 5;
    int start = t * CHUNK;
    int local = 0;
    for (int i = 0; i < CHUNK; i++) {
        int idx = start + i;
        if (idx < NN) local += g_deg[idx];
    }
    int v = local;
    #pragma unroll
    for (int o = 1; o < 32; o <<= 1) {
        int n = __shfl_up_sync(0xFFFFFFFFu, v, o);
        if (lane >= o) v += n;
    }
    if (lane == 31) warp_sums[wid] = v;
    __syncthreads();
    if (wid == 0) {
        int w = warp_sums[lane];
        #pragma unroll
        for (int o = 1; o < 32; o <<= 1) {
            int n = __shfl_up_sync(0xFFFFFFFFu, w, o);
            if (lane >= o) w += n;
        }
        warp_sums[lane] = w;
    }
    __syncthreads();
    int excl = v - local + (wid > 0 ? warp_sums[wid - 1] : 0);
    int run = excl;
    for (int i = 0; i < CHUNK; i++) {
        int idx = start + i;
        if (idx < NN) {
            int dg = g_deg[idx];
            g_row[idx] = run;
            run += dg;
        }
    }
    if (t == 1023) g_row[NN] = run;   // == ET
}

__global__ void scatter_kernel(const int* __restrict__ ei) {
    int e = blockIdx.x * blockDim.x + threadIdx.x;
    if (e >= ET) return;
    int s, d;
    if (e < EE) { s = ei[e]; d = ei[EE + e]; } else { s = d = e - EE; }
    int pos = atomicAdd(&g_cur[d], 1);
    g_srcs[g_row[d] + pos] = s;
}

// ---------------- SGEMM: C[M,N] = A[M,K] @ B[K,N] ----------------
// 128x64 tile, BK=16, 256 threads, 8x4 micro-tile, double-buffered smem.
// Requires: N multiple of 64, K multiple of 16. M arbitrary (guarded).
#define BM 128
#define BN 64
#define BK 16

__global__ __launch_bounds__(256, 2)
void sgemm_kernel(const float* __restrict__ A,
                  const float* __restrict__ B,
                  float* __restrict__ C, int M, int N, int K) {
    __shared__ float As[2][BK][BM];      // 16 KB
    __shared__ float Bs[2][BK][BN];      // 8 KB
    const int tid = threadIdx.x;
    const int tx = tid & 15;             // col group (4 cols)
    const int ty = tid >> 4;             // row group (8 rows)
    const int row0 = blockIdx.y * BM, col0 = blockIdx.x * BN;

    // A-load mapping: 512 float4 per stage, 2 per thread
    const int af0 = tid, af1 = tid + 256;
    const int ar0 = af0 >> 2, ac0 = (af0 & 3) * 4;
    const int ar1 = af1 >> 2, ac1 = (af1 & 3) * 4;
    // B-load mapping: 256 float4 per stage, 1 per thread
    const int br = tid >> 4, bc = (tid & 15) * 4;

    const int nk = K / BK;
    float4 pa0, pa1, pb;

    // prologue: load k-tile 0
    {
        int gr0 = row0 + ar0, gr1 = row0 + ar1;
        pa0 = (gr0 < M) ? *reinterpret_cast<const float4*>(A + (size_t)gr0 * K + ac0)
                        : make_float4(0.f, 0.f, 0.f, 0.f);
        pa1 = (gr1 < M) ? *reinterpret_cast<const float4*>(A + (size_t)gr1 * K + ac1)
                        : make_float4(0.f, 0.f, 0.f, 0.f);
        pb = *reinterpret_cast<const float4*>(B + (size_t)br * N + col0 + bc);
        As[0][ac0 + 0][ar0] = pa0.x; As[0][ac0 + 1][ar0] = pa0.y;
        As[0][ac0 + 2][ar0] = pa0.z; As[0][ac0 + 3][ar0] = pa0.w;
        As[0][ac1 + 0][ar1] = pa1.x; As[0][ac1 + 1][ar1] = pa1.y;
        As[0][ac1 + 2][ar1] = pa1.z; As[0][ac1 + 3][ar1] = pa1.w;
        *reinterpret_cast<float4*>(&Bs[0][br][bc]) = pb;
    }
    __syncthreads();

    float acc[8][4] = {};
    int buf = 0;
    for (int kt = 0; kt < nk; kt++) {
        // prefetch next tile into registers
        if (kt + 1 < nk) {
            int k0 = (kt + 1) * BK;
            int gr0 = row0 + ar0, gr1 = row0 + ar1;
            pa0 = (gr0 < M) ? *reinterpret_cast<const float4*>(A + (size_t)gr0 * K + k0 + ac0)
                            : make_float4(0.f, 0.f, 0.f, 0.f);
            pa1 = (gr1 < M) ? *reinterpret_cast<const float4*>(A + (size_t)gr1 * K + k0 + ac1)
                            : make_float4(0.f, 0.f, 0.f, 0.f);
            pb = *reinterpret_cast<const float4*>(B + (size_t)(k0 + br) * N + col0 + bc);
        }
        // compute on current buffer
        #pragma unroll
        for (int k = 0; k < BK; k++) {
            float a[8], b[4];
            *reinterpret_cast<float4*>(a)     = *reinterpret_cast<const float4*>(&As[buf][k][ty * 8]);
            *reinterpret_cast<float4*>(a + 4) = *reinterpret_cast<const float4*>(&As[buf][k][ty * 8 + 4]);
            *reinterpret_cast<float4*>(b)     = *reinterpret_cast<const float4*>(&Bs[buf][k][tx * 4]);
            #pragma unroll
            for (int i = 0; i < 8; i++)
                #pragma unroll
                for (int j = 0; j < 4; j++)
                    acc[i][j] += a[i] * b[j];
        }
        // store prefetched tile into other buffer
        if (kt + 1 < nk) {
            int nb = buf ^ 1;
            As[nb][ac0 + 0][ar0] = pa0.x; As[nb][ac0 + 1][ar0] = pa0.y;
            As[nb][ac0 + 2][ar0] = pa0.z; As[nb][ac0 + 3][ar0] = pa0.w;
            As[nb][ac1 + 0][ar1] = pa1.x; As[nb][ac1 + 1][ar1] = pa1.y;
            As[nb][ac1 + 2][ar1] = pa1.z; As[nb][ac1 + 3][ar1] = pa1.w;
            *reinterpret_cast<float4*>(&Bs[nb][br][bc]) = pb;
            __syncthreads();
            buf = nb;
        }
    }

    #pragma unroll
    for (int i = 0; i < 8; i++) {
        int gr = row0 + ty * 8 + i;
        if (gr < M) {
            float4 v = make_float4(acc[i][0], acc[i][1], acc[i][2], acc[i][3]);
            *reinterpret_cast<float4*>(C + (size_t)gr * N + col0 + tx * 4) = v;
        }
    }
}

// ---------------- per-node attention coefficients, layer 1 ----------------
__global__ void alpha1_kernel(const float* __restrict__ a_src,
                              const float* __restrict__ a_dst) {
    int w = (blockIdx.x * blockDim.x + threadIdx.x) >> 5;
    int lane = threadIdx.x & 31;
    if (w >= NN) return;
    const float4* hp = reinterpret_cast<const float4*>(g_h1 + (size_t)w * D1);
    float4 v0 = hp[2 * lane];
    float4 v1 = hp[2 * lane + 1];
    int head = lane >> 3;
    int cb = (lane & 7) * 8;
    const float* sa = a_src + head * C1 + cb;
    const float* da = a_dst + head * C1 + cb;
    float ps = v0.x * sa[0] + v0.y * sa[1] + v0.z * sa[2] + v0.w * sa[3]
             + v1.x * sa[4] + v1.y * sa[5] + v1.z * sa[6] + v1.w * sa[7];
    float pd = v0.x * da[0] + v0.y * da[1] + v0.z * da[2] + v0.w * da[3]
             + v1.x * da[4] + v1.y * da[5] + v1.z * da[6] + v1.w * da[7];
    #pragma unroll
    for (int o = 1; o < 8; o <<= 1) {
        ps += __shfl_xor_sync(0xFFFFFFFFu, ps, o);
        pd += __shfl_xor_sync(0xFFFFFFFFu, pd, o);
    }
    if ((lane & 7) == 0) {
        g_as1[w * H1 + head] = ps;
        g_ad1[w * H1 + head] = pd;
    }
}

// ---------------- per-node attention coefficients, layer 2 (H=1) ----------
__global__ void alpha2_kernel(const float* __restrict__ a_src,
                              const float* __restrict__ a_dst) {
    int w = (blockIdx.x * blockDim.x + threadIdx.x) >> 5;
    int lane = threadIdx.x & 31;
    if (w >= NN) return;
    float2 v = reinterpret_cast<const float2*>(g_h2 + (size_t)w * C2)[lane];
    float ps = v.x * a_src[2 * lane] + v.y * a_src[2 * lane + 1];
    float pd = v.x * a_dst[2 * lane] + v.y * a_dst[2 * lane + 1];
    #pragma unroll
    for (int o = 1; o < 32; o <<= 1) {
        ps += __shfl_xor_sync(0xFFFFFFFFu, ps, o);
        pd += __shfl_xor_sync(0xFFFFFFFFu, pd, o);
    }
    if (lane == 0) { g_as2[w] = ps; g_ad2[w] = pd; }
}

// ---------------- fused layer1: softmax + gather-aggregate + bias + relu ---
// one warp per dst node; lane covers 8 cols (head = lane>>3)
__global__ void gat1_fused_kernel(const float* __restrict__ b1) {
    int w = (blockIdx.x * blockDim.x + threadIdx.x) >> 5;
    int lane = threadIdx.x & 31;
    if (w >= NN) return;
    int beg = g_row[w], end = g_row[w + 1];

    float4 adv = *reinterpret_cast<const float4*>(g_ad1 + w * H1);

    // pass A: per-head max over incoming edges
    float4 mx = make_float4(-INFINITY, -INFINITY, -INFINITY, -INFINITY);
    for (int i = beg + lane; i < end; i += 32) {
        int s = g_srcs[i];
        float4 a = *reinterpret_cast<const float4*>(g_as1 + s * H1);
        mx.x = fmaxf(mx.x, lrelu(a.x + adv.x));
        mx.y = fmaxf(mx.y, lrelu(a.y + adv.y));
        mx.z = fmaxf(mx.z, lrelu(a.z + adv.z));
        mx.w = fmaxf(mx.w, lrelu(a.w + adv.w));
    }
    #pragma unroll
    for (int o = 1; o < 32; o <<= 1) {
        mx.x = fmaxf(mx.x, __shfl_xor_sync(0xFFFFFFFFu, mx.x, o));
        mx.y = fmaxf(mx.y, __shfl_xor_sync(0xFFFFFFFFu, mx.y, o));
        mx.z = fmaxf(mx.z, __shfl_xor_sync(0xFFFFFFFFu, mx.z, o));
        mx.w = fmaxf(mx.w, __shfl_xor_sync(0xFFFFFFFFu, mx.w, o));
    }

    // pass B: per-head exp-sum
    float4 sm = make_float4(0.f, 0.f, 0.f, 0.f);
    for (int i = beg + lane; i < end; i += 32) {
        int s = g_srcs[i];
        float4 a = *reinterpret_cast<const float4*>(g_as1 + s * H1);
        sm.x += __expf(lrelu(a.x + adv.x) - mx.x);
        sm.y += __expf(lrelu(a.y + adv.y) - mx.y);
        sm.z += __expf(lrelu(a.z + adv.z) - mx.z);
        sm.w += __expf(lrelu(a.w + adv.w) - mx.w);
    }
    #pragma unroll
    for (int o = 1; o < 32; o <<= 1) {
        sm.x += __shfl_xor_sync(0xFFFFFFFFu, sm.x, o);
        sm.y += __shfl_xor_sync(0xFFFFFFFFu, sm.y, o);
        sm.z += __shfl_xor_sync(0xFFFFFFFFu, sm.z, o);
        sm.w += __shfl_xor_sync(0xFFFFFFFFu, sm.w, o);
    }

    // lane-specific head constants
    int head = lane >> 3;
    float mh  = (head == 0) ? mx.x : (head == 1) ? mx.y : (head == 2) ? mx.z : mx.w;
    float shv = (head == 0) ? sm.x : (head == 1) ? sm.y : (head == 2) ? sm.z : sm.w;
    float adh = (head == 0) ? adv.x : (head == 1) ? adv.y : (head == 2) ? adv.z : adv.w;
    float inv = 1.f / (shv + 1e-16f);

    // pass C: gather + accumulate (all lanes walk all edges together)
    float acc[8] = {};
    for (int i = beg; i < end; i++) {
        int s = g_srcs[i];                               // broadcast load
        float ash = g_as1[s * H1 + head];
        float alpha = __expf(lrelu(ash + adh) - mh) * inv;
        const float4* hp = reinterpret_cast<const float4*>(g_h1 + (size_t)s * D1);
        float4 v0 = hp[2 * lane];
        float4 v1 = hp[2 * lane + 1];
        acc[0] += v0.x * alpha; acc[1] += v0.y * alpha;
        acc[2] += v0.z * alpha; acc[3] += v0.w * alpha;
        acc[4] += v1.x * alpha; acc[5] += v1.y * alpha;
        acc[6] += v1.z * alpha; acc[7] += v1.w * alpha;
    }

    // write with bias + relu
    int cb = lane * 8;
    float* op = g_acc1 + (size_t)w * D1 + cb;
    #pragma unroll
    for (int j = 0; j < 8; j++) {
        float v = acc[j] + b1[cb + j];
        op[j] = v > 0.f ? v : 0.f;
    }
}

// ---------------- fused layer2: softmax + gather-aggregate + bias ----------
// one warp per dst node; lane covers 2 cols
__global__ void gat2_fused_kernel(const float* __restrict__ b2,
                                  float* __restrict__ out) {
    int w = (blockIdx.x * blockDim.x + threadIdx.x) >> 5;
    int lane = threadIdx.x & 31;
    if (w >= NN) return;
    int beg = g_row[w], end = g_row[w + 1];

    float ad = g_ad2[w];

    float mxv = -INFINITY;
    for (int i = beg + lane; i < end; i += 32) {
        int s = g_srcs[i];
        mxv = fmaxf(mxv, lrelu(g_as2[s] + ad));
    }
    #pragma unroll
    for (int o = 1; o < 32; o <<= 1)
        mxv = fmaxf(mxv, __shfl_xor_sync(0xFFFFFFFFu, mxv, o));

    float smv = 0.f;
    for (int i = beg + lane; i < end; i += 32) {
        int s = g_srcs[i];
        smv += __expf(lrelu(g_as2[s] + ad) - mxv);
    }
    #pragma unroll
    for (int o = 1; o < 32; o <<= 1)
        smv += __shfl_xor_sync(0xFFFFFFFFu, smv, o);
    float inv = 1.f / (smv + 1e-16f);

    float a0 = 0.f, a1 = 0.f;
    for (int i = beg; i < end; i++) {
        int s = g_srcs[i];
        float alpha = __expf(lrelu(g_as2[s] + ad) - mxv) * inv;
        float2 v = reinterpret_cast<const float2*>(g_h2 + (size_t)s * C2)[lane];
        a0 += v.x * alpha;
        a1 += v.y * alpha;
    }
    float* op = out + (size_t)w * C2 + 2 * lane;
    op[0] = a0 + b2[2 * lane];
    op[1] = a1 + b2[2 * lane + 1];
}

extern "C" void kernel_launch(void* const* d_in, const int* in_sizes, int n_in,
                              void* d_out, int out_size) {
    const float* x     = (const float*)d_in[0];
    const int*   ei    = (const int*)d_in[1];     // int32
    const float* W1    = (const float*)d_in[2];
    const float* at_s1 = (const float*)d_in[3];
    const float* at_d1 = (const float*)d_in[4];
    const float* b1    = (const float*)d_in[5];
    const float* W2    = (const float*)d_in[6];
    const float* at_s2 = (const float*)d_in[7];
    const float* at_d2 = (const float*)d_in[8];
    const float* b2    = (const float*)d_in[9];
    float* out = (float*)d_out;

    static float* p_h1   = nullptr;
    static float* p_acc1 = nullptr;
    static float* p_h2   = nullptr;
    if (!p_h1) {   // address lookup only (no allocation)
        cudaGetSymbolAddress((void**)&p_h1, g_h1);
        cudaGetSymbolAddress((void**)&p_acc1, g_acc1);
        cudaGetSymbolAddress((void**)&p_h2, g_h2);
    }

    // ---- CSR build (shared by both layers) ----
    zero_counts_kernel<<<(NN + 255) / 256, 256>>>();
    hist_kernel<<<(ET + 255) / 256, 256>>>(ei);
    scan_kernel<<<1, 1024>>>();
    scatter_kernel<<<(ET + 255) / 256, 256>>>(ei);

    // ---- layer 1 ----
    sgemm_kernel<<<dim3(D1 / BN, (NN + BM - 1) / BM), 256>>>(x, W1, p_h1, NN, D1, IN1);
    alpha1_kernel<<<(NN + 7) / 8, 256>>>(at_s1, at_d1);
    gat1_fused_kernel<<<(NN + 7) / 8, 256>>>(b1);

    // ---- layer 2 ----
    sgemm_kernel<<<dim3(C2 / BN, (NN + BM - 1) / BM), 256>>>(p_acc1, W2, p_h2, NN, C2, D1);
    alpha2_kernel<<<(NN + 7) / 8, 256>>>(at_s2, at_d2);
    gat2_fused_kernel<<<(NN + 7) / 8, 256>>>(b2, out);
}

// round 5
// speedup vs baseline: 4.3405x; 1.1669x over previous
#include <cuda_runtime.h>
#include <cuda_fp16.h>
#include <math.h>

// Problem constants (fixed for this dataset)
#define NN 50000
#define EE 800000
#define ET (EE + NN)      // 850000 edges incl. self loops
#define H1 4
#define C1 64
#define D1 256            // H1*C1
#define C2 64
#define IN1 128
#define NEG_SLOPE 0.2f

// ---------------- scratch (device globals, no runtime alloc) ----------------
__device__ float   g_h1 [(size_t)NN * D1];       // x @ W1 (fp32, for alpha dots)
__device__ __half2 g_h1h[(size_t)NN * D1 / 2];   // fp16 copy for gather
__device__ float   g_acc1[(size_t)NN * D1];      // layer1 output (post bias+relu)
__device__ float   g_as1[NN * H1];
__device__ float   g_ad1[NN * H1];
__device__ float   g_h2 [(size_t)NN * C2];
__device__ __half2 g_h2h[(size_t)NN * C2 / 2];
__device__ float   g_as2[NN];
__device__ float   g_ad2[NN];
// CSR by dst
__device__ int g_deg[NN];
__device__ int g_cur[NN];
__device__ int g_row[NN + 1];
__device__ int g_srcs[ET];

__device__ __forceinline__ float lrelu(float v) {
    return v > 0.f ? v : NEG_SLOPE * v;
}

// ---------------- CSR build ----------------
__global__ void zero_counts_kernel() {
    int i = blockIdx.x * blockDim.x + threadIdx.x;
    if (i < NN) { g_deg[i] = 0; g_cur[i] = 0; }
}

__global__ void hist_kernel(const int* __restrict__ ei) {
    int e = blockIdx.x * blockDim.x + threadIdx.x;
    if (e >= ET) return;
    int d = (e < EE) ? ei[EE + e] : (e - EE);
    atomicAdd(&g_deg[d], 1);
}

// single-block exclusive scan of g_deg -> g_row  (1024 threads)
__global__ void scan_kernel() {
    __shared__ int warp_sums[32];
    const int CHUNK = (NN + 1023) / 1024;   // 49
    int t = threadIdx.x;
    int lane = t & 31, wid = t >> 5;
    int start = t * CHUNK;
    int local = 0;
    for (int i = 0; i < CHUNK; i++) {
        int idx = start + i;
        if (idx < NN) local += g_deg[idx];
    }
    int v = local;
    #pragma unroll
    for (int o = 1; o < 32; o <<= 1) {
        int n = __shfl_up_sync(0xFFFFFFFFu, v, o);
        if (lane >= o) v += n;
    }
    if (lane == 31) warp_sums[wid] = v;
    __syncthreads();
    if (wid == 0) {
        int w = warp_sums[lane];
        #pragma unroll
        for (int o = 1; o < 32; o <<= 1) {
            int n = __shfl_up_sync(0xFFFFFFFFu, w, o);
            if (lane >= o) w += n;
        }
        warp_sums[lane] = w;
    }
    __syncthreads();
    int excl = v - local + (wid > 0 ? warp_sums[wid - 1] : 0);
    int run = excl;
    for (int i = 0; i < CHUNK; i++) {
        int idx = start + i;
        if (idx < NN) {
            int dg = g_deg[idx];
            g_row[idx] = run;
            run += dg;
        }
    }
    if (t == 1023) g_row[NN] = run;   // == ET
}

__global__ void scatter_kernel(const int* __restrict__ ei) {
    int e = blockIdx.x * blockDim.x + threadIdx.x;
    if (e >= ET) return;
    int s, d;
    if (e < EE) { s = ei[e]; d = ei[EE + e]; } else { s = d = e - EE; }
    int pos = atomicAdd(&g_cur[d], 1);
    g_srcs[g_row[d] + pos] = s;
}

// ---------------- SGEMM: C[M,N] = A[M,K] @ B[K,N] (+ fp16 copy) -----------
// 128x64 tile, BK=16, 256 threads, 8x4 micro-tile, double-buffered smem.
#define BM 128
#define BN 64
#define BK 16

__global__ __launch_bounds__(256, 2)
void sgemm_kernel(const float* __restrict__ A,
                  const float* __restrict__ B,
                  float* __restrict__ C,
                  __half2* __restrict__ Ch,
                  int M, int N, int K) {
    __shared__ float As[2][BK][BM];      // 16 KB
    __shared__ float Bs[2][BK][BN];      // 8 KB
    const int tid = threadIdx.x;
    const int tx = tid & 15;             // col group (4 cols)
    const int ty = tid >> 4;             // row group (8 rows)
    const int row0 = blockIdx.y * BM, col0 = blockIdx.x * BN;

    const int af0 = tid, af1 = tid + 256;
    const int ar0 = af0 >> 2, ac0 = (af0 & 3) * 4;
    const int ar1 = af1 >> 2, ac1 = (af1 & 3) * 4;
    const int br = tid >> 4, bc = (tid & 15) * 4;

    const int nk = K / BK;
    float4 pa0, pa1, pb;

    {
        int gr0 = row0 + ar0, gr1 = row0 + ar1;
        pa0 = (gr0 < M) ? *reinterpret_cast<const float4*>(A + (size_t)gr0 * K + ac0)
                        : make_float4(0.f, 0.f, 0.f, 0.f);
        pa1 = (gr1 < M) ? *reinterpret_cast<const float4*>(A + (size_t)gr1 * K + ac1)
                        : make_float4(0.f, 0.f, 0.f, 0.f);
        pb = *reinterpret_cast<const float4*>(B + (size_t)br * N + col0 + bc);
        As[0][ac0 + 0][ar0] = pa0.x; As[0][ac0 + 1][ar0] = pa0.y;
        As[0][ac0 + 2][ar0] = pa0.z; As[0][ac0 + 3][ar0] = pa0.w;
        As[0][ac1 + 0][ar1] = pa1.x; As[0][ac1 + 1][ar1] = pa1.y;
        As[0][ac1 + 2][ar1] = pa1.z; As[0][ac1 + 3][ar1] = pa1.w;
        *reinterpret_cast<float4*>(&Bs[0][br][bc]) = pb;
    }
    __syncthreads();

    float acc[8][4] = {};
    int buf = 0;
    for (int kt = 0; kt < nk; kt++) {
        if (kt + 1 < nk) {
            int k0 = (kt + 1) * BK;
            int gr0 = row0 + ar0, gr1 = row0 + ar1;
            pa0 = (gr0 < M) ? *reinterpret_cast<const float4*>(A + (size_t)gr0 * K + k0 + ac0)
                            : make_float4(0.f, 0.f, 0.f, 0.f);
            pa1 = (gr1 < M) ? *reinterpret_cast<const float4*>(A + (size_t)gr1 * K + k0 + ac1)
                            : make_float4(0.f, 0.f, 0.f, 0.f);
            pb = *reinterpret_cast<const float4*>(B + (size_t)(k0 + br) * N + col0 + bc);
        }
        #pragma unroll
        for (int k = 0; k < BK; k++) {
            float a[8], b[4];
            *reinterpret_cast<float4*>(a)     = *reinterpret_cast<const float4*>(&As[buf][k][ty * 8]);
            *reinterpret_cast<float4*>(a + 4) = *reinterpret_cast<const float4*>(&As[buf][k][ty * 8 + 4]);
            *reinterpret_cast<float4*>(b)     = *reinterpret_cast<const float4*>(&Bs[buf][k][tx * 4]);
            #pragma unroll
            for (int i = 0; i < 8; i++)
                #pragma unroll
                for (int j = 0; j < 4; j++)
                    acc[i][j] += a[i] * b[j];
        }
        if (kt + 1 < nk) {
            int nb = buf ^ 1;
            As[nb][ac0 + 0][ar0] = pa0.x; As[nb][ac0 + 1][ar0] = pa0.y;
            As[nb][ac0 + 2][ar0] = pa0.z; As[nb][ac0 + 3][ar0] = pa0.w;
            As[nb][ac1 + 0][ar1] = pa1.x; As[nb][ac1 + 1][ar1] = pa1.y;
            As[nb][ac1 + 2][ar1] = pa1.z; As[nb][ac1 + 3][ar1] = pa1.w;
            *reinterpret_cast<float4*>(&Bs[nb][br][bc]) = pb;
            __syncthreads();
            buf = nb;
        }
    }

    #pragma unroll
    for (int i = 0; i < 8; i++) {
        int gr = row0 + ty * 8 + i;
        if (gr < M) {
            float4 v = make_float4(acc[i][0], acc[i][1], acc[i][2], acc[i][3]);
            *reinterpret_cast<float4*>(C + (size_t)gr * N + col0 + tx * 4) = v;
            __half2* dst = Ch + ((size_t)gr * N + col0 + tx * 4) / 2;
            dst[0] = __floats2half2_rn(acc[i][0], acc[i][1]);
            dst[1] = __floats2half2_rn(acc[i][2], acc[i][3]);
        }
    }
}

// ---------------- per-node attention coefficients, layer 1 ----------------
__global__ void alpha1_kernel(const float* __restrict__ a_src,
                              const float* __restrict__ a_dst) {
    int w = (blockIdx.x * blockDim.x + threadIdx.x) >> 5;
    int lane = threadIdx.x & 31;
    if (w >= NN) return;
    const float4* hp = reinterpret_cast<const float4*>(g_h1 + (size_t)w * D1);
    float4 v0 = hp[2 * lane];
    float4 v1 = hp[2 * lane + 1];
    int head = lane >> 3;
    int cb = (lane & 7) * 8;
    const float* sa = a_src + head * C1 + cb;
    const float* da = a_dst + head * C1 + cb;
    float ps = v0.x * sa[0] + v0.y * sa[1] + v0.z * sa[2] + v0.w * sa[3]
             + v1.x * sa[4] + v1.y * sa[5] + v1.z * sa[6] + v1.w * sa[7];
    float pd = v0.x * da[0] + v0.y * da[1] + v0.z * da[2] + v0.w * da[3]
             + v1.x * da[4] + v1.y * da[5] + v1.z * da[6] + v1.w * da[7];
    #pragma unroll
    for (int o = 1; o < 8; o <<= 1) {
        ps += __shfl_xor_sync(0xFFFFFFFFu, ps, o);
        pd += __shfl_xor_sync(0xFFFFFFFFu, pd, o);
    }
    if ((lane & 7) == 0) {
        g_as1[w * H1 + head] = ps;
        g_ad1[w * H1 + head] = pd;
    }
}

// ---------------- per-node attention coefficients, layer 2 (H=1) ----------
__global__ void alpha2_kernel(const float* __restrict__ a_src,
                              const float* __restrict__ a_dst) {
    int w = (blockIdx.x * blockDim.x + threadIdx.x) >> 5;
    int lane = threadIdx.x & 31;
    if (w >= NN) return;
    float2 v = reinterpret_cast<const float2*>(g_h2 + (size_t)w * C2)[lane];
    float ps = v.x * a_src[2 * lane] + v.y * a_src[2 * lane + 1];
    float pd = v.x * a_dst[2 * lane] + v.y * a_dst[2 * lane + 1];
    #pragma unroll
    for (int o = 1; o < 32; o <<= 1) {
        ps += __shfl_xor_sync(0xFFFFFFFFu, ps, o);
        pd += __shfl_xor_sync(0xFFFFFFFFu, pd, o);
    }
    if (lane == 0) { g_as2[w] = ps; g_ad2[w] = pd; }
}

// ---------------- fused layer1: softmax + fp16 gather + bias + relu -------
// one warp per dst node; lane covers 8 cols (head = lane>>3)
__global__ void gat1_fused_kernel(const float* __restrict__ b1) {
    int w = (blockIdx.x * blockDim.x + threadIdx.x) >> 5;
    int lane = threadIdx.x & 31;
    if (w >= NN) return;
    int beg = g_row[w], end = g_row[w + 1];

    float4 adv = *reinterpret_cast<const float4*>(g_ad1 + w * H1);

    // pass A: per-head max over incoming edges
    float4 mx = make_float4(-INFINITY, -INFINITY, -INFINITY, -INFINITY);
    for (int i = beg + lane; i < end; i += 32) {
        int s = g_srcs[i];
        float4 a = *reinterpret_cast<const float4*>(g_as1 + s * H1);
        mx.x = fmaxf(mx.x, lrelu(a.x + adv.x));
        mx.y = fmaxf(mx.y, lrelu(a.y + adv.y));
        mx.z = fmaxf(mx.z, lrelu(a.z + adv.z));
        mx.w = fmaxf(mx.w, lrelu(a.w + adv.w));
    }
    #pragma unroll
    for (int o = 1; o < 32; o <<= 1) {
        mx.x = fmaxf(mx.x, __shfl_xor_sync(0xFFFFFFFFu, mx.x, o));
        mx.y = fmaxf(mx.y, __shfl_xor_sync(0xFFFFFFFFu, mx.y, o));
        mx.z = fmaxf(mx.z, __shfl_xor_sync(0xFFFFFFFFu, mx.z, o));
        mx.w = fmaxf(mx.w, __shfl_xor_sync(0xFFFFFFFFu, mx.w, o));
    }

    // pass B: per-head exp-sum
    float4 sm = make_float4(0.f, 0.f, 0.f, 0.f);
    for (int i = beg + lane; i < end; i += 32) {
        int s = g_srcs[i];
        float4 a = *reinterpret_cast<const float4*>(g_as1 + s * H1);
        sm.x += __expf(lrelu(a.x + adv.x) - mx.x);
        sm.y += __expf(lrelu(a.y + adv.y) - mx.y);
        sm.z += __expf(lrelu(a.z + adv.z) - mx.z);
        sm.w += __expf(lrelu(a.w + adv.w) - mx.w);
    }
    #pragma unroll
    for (int o = 1; o < 32; o <<= 1) {
        sm.x += __shfl_xor_sync(0xFFFFFFFFu, sm.x, o);
        sm.y += __shfl_xor_sync(0xFFFFFFFFu, sm.y, o);
        sm.z += __shfl_xor_sync(0xFFFFFFFFu, sm.z, o);
        sm.w += __shfl_xor_sync(0xFFFFFFFFu, sm.w, o);
    }

    int head = lane >> 3;
    float mh  = (head == 0) ? mx.x : (head == 1) ? mx.y : (head == 2) ? mx.z : mx.w;
    float shv = (head == 0) ? sm.x : (head == 1) ? sm.y : (head == 2) ? sm.z : sm.w;
    float adh = (head == 0) ? adv.x : (head == 1) ? adv.y : (head == 2) ? adv.z : adv.w;
    float inv = 1.f / (shv + 1e-16f);

    // pass C: fp16 gather + fp32 accumulate
    float acc[8] = {};
    #pragma unroll 2
    for (int i = beg; i < end; i++) {
        int s = g_srcs[i];                               // broadcast load
        float ash = g_as1[s * H1 + head];
        float alpha = __expf(lrelu(ash + adh) - mh) * inv;
        const uint4* hp = reinterpret_cast<const uint4*>(g_h1h + (size_t)s * (D1 / 2));
        uint4 u = hp[lane];
        float2 f0 = __half22float2(*reinterpret_cast<__half2*>(&u.x));
        float2 f1 = __half22float2(*reinterpret_cast<__half2*>(&u.y));
        float2 f2 = __half22float2(*reinterpret_cast<__half2*>(&u.z));
        float2 f3 = __half22float2(*reinterpret_cast<__half2*>(&u.w));
        acc[0] += f0.x * alpha; acc[1] += f0.y * alpha;
        acc[2] += f1.x * alpha; acc[3] += f1.y * alpha;
        acc[4] += f2.x * alpha; acc[5] += f2.y * alpha;
        acc[6] += f3.x * alpha; acc[7] += f3.y * alpha;
    }

    int cb = lane * 8;
    float* op = g_acc1 + (size_t)w * D1 + cb;
    #pragma unroll
    for (int j = 0; j < 8; j++) {
        float v = acc[j] + b1[cb + j];
        op[j] = v > 0.f ? v : 0.f;
    }
}

// ---------------- fused layer2: softmax + fp16 gather + bias --------------
// one warp per dst node; lane covers 2 cols
__global__ void gat2_fused_kernel(const float* __restrict__ b2,
                                  float* __restrict__ out) {
    int w = (blockIdx.x * blockDim.x + threadIdx.x) >> 5;
    int lane = threadIdx.x & 31;
    if (w >= NN) return;
    int beg = g_row[w], end = g_row[w + 1];

    float ad = g_ad2[w];

    float mxv = -INFINITY;
    for (int i = beg + lane; i < end; i += 32) {
        int s = g_srcs[i];
        mxv = fmaxf(mxv, lrelu(g_as2[s] + ad));
    }
    #pragma unroll
    for (int o = 1; o < 32; o <<= 1)
        mxv = fmaxf(mxv, __shfl_xor_sync(0xFFFFFFFFu, mxv, o));

    float smv = 0.f;
    for (int i = beg + lane; i < end; i += 32) {
        int s = g_srcs[i];
        smv += __expf(lrelu(g_as2[s] + ad) - mxv);
    }
    #pragma unroll
    for (int o = 1; o < 32; o <<= 1)
        smv += __shfl_xor_sync(0xFFFFFFFFu, smv, o);
    float inv = 1.f / (smv + 1e-16f);

    float a0 = 0.f, a1 = 0.f;
    #pragma unroll 2
    for (int i = beg; i < end; i++) {
        int s = g_srcs[i];
        float alpha = __expf(lrelu(g_as2[s] + ad) - mxv) * inv;
        __half2 hv = g_h2h[(size_t)s * (C2 / 2) + lane];
        float2 v = __half22float2(hv);
        a0 += v.x * alpha;
        a1 += v.y * alpha;
    }
    float* op = out + (size_t)w * C2 + 2 * lane;
    op[0] = a0 + b2[2 * lane];
    op[1] = a1 + b2[2 * lane + 1];
}

extern "C" void kernel_launch(void* const* d_in, const int* in_sizes, int n_in,
                              void* d_out, int out_size) {
    const float* x     = (const float*)d_in[0];
    const int*   ei    = (const int*)d_in[1];     // int32
    const float* W1    = (const float*)d_in[2];
    const float* at_s1 = (const float*)d_in[3];
    const float* at_d1 = (const float*)d_in[4];
    const float* b1    = (const float*)d_in[5];
    const float* W2    = (const float*)d_in[6];
    const float* at_s2 = (const float*)d_in[7];
    const float* at_d2 = (const float*)d_in[8];
    const float* b2    = (const float*)d_in[9];
    float* out = (float*)d_out;

    static float*   p_h1   = nullptr;
    static float*   p_acc1 = nullptr;
    static float*   p_h2   = nullptr;
    static __half2* p_h1h  = nullptr;
    static __half2* p_h2h  = nullptr;
    static cudaStream_t s_side = nullptr;
    static cudaEvent_t  ev_root = nullptr, ev_csr = nullptr;
    if (!p_h1) {   // address lookup + stream/event creation (first call is
                   // the un-captured correctness run; no device mem alloc)
        cudaGetSymbolAddress((void**)&p_h1, g_h1);
        cudaGetSymbolAddress((void**)&p_acc1, g_acc1);
        cudaGetSymbolAddress((void**)&p_h2, g_h2);
        cudaGetSymbolAddress((void**)&p_h1h, g_h1h);
        cudaGetSymbolAddress((void**)&p_h2h, g_h2h);
        cudaStreamCreateWithFlags(&s_side, cudaStreamNonBlocking);
        cudaEventCreateWithFlags(&ev_root, cudaEventDisableTiming);
        cudaEventCreateWithFlags(&ev_csr, cudaEventDisableTiming);
    }

    // ---- fork: CSR build on side stream, overlapped with layer-1 GEMM ----
    cudaEventRecord(ev_root, (cudaStream_t)0);
    cudaStreamWaitEvent(s_side, ev_root, 0);
    zero_counts_kernel<<<(NN + 255) / 256, 256, 0, s_side>>>();
    hist_kernel<<<(ET + 255) / 256, 256, 0, s_side>>>(ei);
    scan_kernel<<<1, 1024, 0, s_side>>>();
    scatter_kernel<<<(ET + 255) / 256, 256, 0, s_side>>>(ei);
    cudaEventRecord(ev_csr, s_side);

    // ---- layer 1 (main stream) ----
    sgemm_kernel<<<dim3(D1 / BN, (NN + BM - 1) / BM), 256>>>(x, W1, p_h1, p_h1h, NN, D1, IN1);
    alpha1_kernel<<<(NN + 7) / 8, 256>>>(at_s1, at_d1);
    cudaStreamWaitEvent((cudaStream_t)0, ev_csr, 0);   // join CSR
    gat1_fused_kernel<<<(NN + 7) / 8, 256>>>(b1);

    // ---- layer 2 ----
    sgemm_kernel<<<dim3(C2 / BN, (NN + BM - 1) / BM), 256>>>(p_acc1, W2, p_h2, p_h2h, NN, C2, D1);
    alpha2_kernel<<<(NN + 7) / 8, 256>>>(at_s2, at_d2);
    gat2_fused_kernel<<<(NN + 7) / 8, 256>>>(b2, out);
}